// round 4
// baseline (speedup 1.0000x reference)
#include <cuda_runtime.h>
#include <cstdint>

// Problem constants
#define SIG_HW   256
#define CIN      64
#define COUT     64
#define KS       31
#define PADK     15
#define NBATCH   8

// weights re-layout scratch: [ky][kx][o][c], tf32-rounded bits stored as float
__device__ float g_w2[KS * KS * COUT * CIN];

__device__ __forceinline__ unsigned f2tf(float x) {
    unsigned r;
    asm("cvt.rna.tf32.f32 %0, %1;" : "=r"(r) : "f"(x));
    return r;
}

// ---------------------------------------------------------------------------
// Pre-kernel: w[o][c][ky][kx] (fp32) -> g_w2[((ky*31+kx)*64 + o)*64 + c] (tf32)
// Read-coalesced over the input layout.
// ---------------------------------------------------------------------------
__global__ void prep_weights(const float* __restrict__ w) {
    int idx = blockIdx.x * 256 + threadIdx.x;
    if (idx >= KS * KS * COUT * CIN) return;
    int kx = idx % KS;
    int t  = idx / KS;
    int ky = t % KS;  t /= KS;
    int c  = t % CIN;
    int o  = t / CIN;
    unsigned v = f2tf(w[idx]);
    g_w2[((ky * KS + kx) * COUT + o) * CIN + c] = __uint_as_float(v);
}

// ---------------------------------------------------------------------------
// Main kernel: one block per (b, y). Computes all 64 out-channels for one
// full output row (256 x). GEMM: C[m=o(64)][n=x(256)] over K=(c,ky,kx).
//   A operand (row-major m16k8) = weight tile  sW[o][c]   (per ky,kx)
//   B operand (col-major k8n8)  = signal tile  sA[c][x+kx] (per ky)
// 8 warps: 2 (m: 32 o each) x 4 (n: 64 x each). Per warp: 2 m16 x 8 n8 tiles.
// ---------------------------------------------------------------------------
#define SA_STRIDE 296   // 296 % 32 == 8 -> conflict-free B-fragment loads
#define SW_STRIDE 68    // 68*4 % 128: (4*o + c) distinct banks for A frags
#define SA_ELEMS  (CIN * SA_STRIDE)
#define SW_ELEMS  (COUT * SW_STRIDE)

__device__ __forceinline__ void mma_tf32(float* d, const unsigned* a,
                                         unsigned b0, unsigned b1) {
    asm volatile(
        "mma.sync.aligned.m16n8k8.row.col.f32.tf32.tf32.f32 "
        "{%0,%1,%2,%3}, {%4,%5,%6,%7}, {%8,%9}, {%0,%1,%2,%3};\n"
        : "+f"(d[0]), "+f"(d[1]), "+f"(d[2]), "+f"(d[3])
        : "r"(a[0]), "r"(a[1]), "r"(a[2]), "r"(a[3]), "r"(b0), "r"(b1));
}

extern __shared__ float smem_dyn[];

__global__ __launch_bounds__(256) void conv_main(
    const float* __restrict__ sig,
    const float* __restrict__ bias,
    float* __restrict__ out)
{
    float* sA = smem_dyn;              // [CIN][SA_STRIDE] signal row (tf32 bits)
    float* sW = smem_dyn + SA_ELEMS;   // [COUT][SW_STRIDE] weight tile (tf32 bits)

    const int y    = blockIdx.x;
    const int b    = blockIdx.y;
    const int tid  = threadIdx.x;
    const int lane = tid & 31;
    const int warp = tid >> 5;
    const int wm   = warp & 1;   // o half (0..1)
    const int wn   = warp >> 1;  // x quarter (0..3)
    const int g    = lane >> 2;  // groupID
    const int t4   = lane & 3;   // thread-in-group

    float acc[2][8][4];
#pragma unroll
    for (int mt = 0; mt < 2; mt++)
#pragma unroll
        for (int nt = 0; nt < 8; nt++)
#pragma unroll
            for (int r = 0; r < 4; r++) acc[mt][nt][r] = 0.f;

    const float* sigb = sig + (long)b * CIN * SIG_HW * SIG_HW;

    for (int ky = 0; ky < KS; ky++) {
        const int iy = y + ky - PADK;
        if (iy < 0 || iy >= SIG_HW) continue;  // uniform per block

        __syncthreads();  // prior kx-loop done reading sA
        {
            // sA[c][j] = tf32(signal[b,c,iy,j-15]) for j in [0,286)
            const int c = tid >> 2;
            const int q = tid & 3;
            const float* src = sigb + (long)c * (SIG_HW * SIG_HW) + (long)iy * SIG_HW;
            float* dst = sA + c * SA_STRIDE;
            for (int j = q; j < SIG_HW + KS - 1; j += 4) {
                int ix = j - PADK;
                float v = (ix >= 0 && ix < SIG_HW) ? __ldg(src + ix) : 0.f;
                dst[j] = __uint_as_float(f2tf(v));
            }
        }

        for (int kx = 0; kx < KS; kx++) {
            __syncthreads();  // prior mma done reading sW; sA visible on kx==0
            {
                // Load 64x64 weight tile (16 KB) via float4
                const float4* wsrc =
                    (const float4*)(g_w2 + ((ky * KS + kx) << 12));
#pragma unroll
                for (int i = 0; i < 4; i++) {
                    int e = tid + i * 256;          // [0,1024)
                    float4 v = wsrc[e];
                    int o  = e >> 4;
                    int c4 = (e & 15) << 2;
                    *(float4*)(sW + o * SW_STRIDE + c4) = v;
                }
            }
            __syncthreads();

#pragma unroll
            for (int kc = 0; kc < 8; kc++) {
                unsigned a[2][4];
#pragma unroll
                for (int mt = 0; mt < 2; mt++) {
                    const int o0 = wm * 32 + mt * 16 + g;
                    const int c0 = kc * 8 + t4;
                    const float* p = sW + o0 * SW_STRIDE + c0;
                    a[mt][0] = __float_as_uint(p[0]);
                    a[mt][1] = __float_as_uint(p[8 * SW_STRIDE]);
                    a[mt][2] = __float_as_uint(p[4]);
                    a[mt][3] = __float_as_uint(p[8 * SW_STRIDE + 4]);
                }
#pragma unroll
                for (int nt = 0; nt < 8; nt++) {
                    const int x0 = wn * 64 + nt * 8 + g + kx;
                    const int c0 = kc * 8 + t4;
                    const float* p = sA + c0 * SA_STRIDE + x0;
                    unsigned b0 = __float_as_uint(p[0]);
                    unsigned b1 = __float_as_uint(p[4 * SA_STRIDE]);
                    mma_tf32(acc[0][nt], a[0], b0, b1);
                    mma_tf32(acc[1][nt], a[1], b0, b1);
                }
            }
        }
    }

    // Epilogue: add bias, write out[b][o][y][x]
#pragma unroll
    for (int mt = 0; mt < 2; mt++) {
#pragma unroll
        for (int r = 0; r < 2; r++) {
            const int o = wm * 32 + mt * 16 + r * 8 + g;
            const float bv = __ldg(bias + o);
            float* orow = out + (((long)(b * COUT + o)) * SIG_HW + y) * SIG_HW;
#pragma unroll
            for (int nt = 0; nt < 8; nt++) {
                const int x = wn * 64 + nt * 8 + t4 * 2;
                float2 v;
                v.x = acc[mt][nt][r * 2 + 0] + bv;
                v.y = acc[mt][nt][r * 2 + 1] + bv;
                *(float2*)(orow + x) = v;
            }
        }
    }
}

// ---------------------------------------------------------------------------
extern "C" void kernel_launch(void* const* d_in, const int* in_sizes, int n_in,
                              void* d_out, int out_size) {
    const float* sig  = (const float*)d_in[0];
    const float* w    = (const float*)d_in[1];
    const float* bias = (const float*)d_in[2];
    float* out        = (float*)d_out;

    // 1) weight re-layout + tf32 rounding
    const int wtot = KS * KS * COUT * CIN;
    prep_weights<<<(wtot + 255) / 256, 256>>>(w);

    // 2) main conv
    const size_t smem_bytes = (size_t)(SA_ELEMS + SW_ELEMS) * sizeof(float); // 93,184
    cudaFuncSetAttribute(conv_main, cudaFuncAttributeMaxDynamicSharedMemorySize,
                         (int)smem_bytes);
    dim3 grid(SIG_HW, NBATCH);  // (y, b)
    conv_main<<<grid, 256, smem_bytes>>>(sig, bias, out);
}

// round 7
// speedup vs baseline: 1.1230x; 1.1230x over previous
#include <cuda_runtime.h>
#include <cstdint>

// Problem constants
#define SIG_HW   256
#define CIN      64
#define COUT     64
#define KS       31
#define PADK     15
#define NBATCH   8

// smem geometry
#define SA_STRIDE 296   // floats per signal row-channel; 296 % 32 == 8 -> conflict-free frags
#define SW_STRIDE 68    // floats per weight o-row
#define SA_ROW_ELEMS (CIN * SA_STRIDE)            // one signal row tile (64 x 296)
#define SW_TILE_ELEMS (COUT * SW_STRIDE)          // one weight tile (64 x 68)
#define SMEM_FLOATS (2 * SA_ROW_ELEMS + 2 * SW_TILE_ELEMS)  // 46,592 floats = 186,368 B

__device__ float g_w2[KS * KS * COUT * CIN];

__device__ __forceinline__ unsigned f2tf(float x) {
    unsigned r;
    asm("cvt.rna.tf32.f32 %0, %1;" : "=r"(r) : "f"(x));
    return r;
}

// ---------------------------------------------------------------------------
// Pre-kernel: w[o][c][ky][kx] (fp32) -> g_w2[((ky*31+kx)*64 + o)*64 + c] (tf32)
// ---------------------------------------------------------------------------
__global__ void prep_weights(const float* __restrict__ w) {
    int idx = blockIdx.x * 256 + threadIdx.x;
    if (idx >= KS * KS * COUT * CIN) return;
    int kx = idx % KS;
    int t  = idx / KS;
    int ky = t % KS;  t /= KS;
    int c  = t % CIN;
    int o  = t / CIN;
    unsigned v = f2tf(w[idx]);
    g_w2[((ky * KS + kx) * COUT + o) * CIN + c] = __uint_as_float(v);
}

__device__ __forceinline__ void mma_tf32(float* d, const unsigned* a,
                                         unsigned b0, unsigned b1) {
    asm volatile(
        "mma.sync.aligned.m16n8k8.row.col.f32.tf32.tf32.f32 "
        "{%0,%1,%2,%3}, {%4,%5,%6,%7}, {%8,%9}, {%0,%1,%2,%3};\n"
        : "+f"(d[0]), "+f"(d[1]), "+f"(d[2]), "+f"(d[3])
        : "r"(a[0]), "r"(a[1]), "r"(a[2]), "r"(a[3]), "r"(b0), "r"(b1));
}

extern __shared__ float smem_dyn[];

// ---------------------------------------------------------------------------
// Block = (y-pair, batch). Computes out[b][0..63][y..y+1][0..255].
// GEMM: C[m=o(64)][n=x(256)], K=(c,ky,kx). Weight tile (ky,kx) serves BOTH
// output rows: y pairs with signal row j=ky, y+1 pairs with row j=ky+1.
// 8 warps, each covering all 4 m16-tiles x 4 n8-tiles (32 x per warp) x 2 y.
// A-frags reused 8x, B-frags 4x -> 1.0 LDS.32 per MMA.
// ---------------------------------------------------------------------------
__global__ void __launch_bounds__(256, 1) conv_main(
    const float* __restrict__ sig,
    const float* __restrict__ bias,
    float* __restrict__ out)
{
    float* sA = smem_dyn;                       // [2][CIN][SA_STRIDE] signal ring
    float* sW = smem_dyn + 2 * SA_ROW_ELEMS;    // [2][COUT][SW_STRIDE] weights

    const int tid  = threadIdx.x;
    const int lane = tid & 31;
    const int warp = tid >> 5;       // 0..7: x-slice of 32
    const int g    = lane >> 2;      // groupID
    const int t4   = lane & 3;       // thread-in-group
    const int y    = blockIdx.x * 2;
    const int b    = blockIdx.y;

    float acc[4][4][8];              // [mt][nt][y01*4 + frag]
#pragma unroll
    for (int mt = 0; mt < 4; mt++)
#pragma unroll
        for (int nt = 0; nt < 4; nt++)
#pragma unroll
            for (int r = 0; r < 8; r++) acc[mt][nt][r] = 0.f;

    const float* sigb = sig + ((long)b << 22);   // b * 64 * 256 * 256

    // signal row loader: row index j (0..31), iy = y-15+j -> sA[slot]
    auto load_row = [&](int j) {
        const int iy = y - PADK + j;
        const bool vy = (iy >= 0 && iy < SIG_HW);
        float* dst0 = sA + (j & 1) * SA_ROW_ELEMS;
        const int c = tid >> 2;
        const int q4 = tid & 3;
        const float* src = sigb + ((long)c << 16) + ((long)iy << 8);
        float* dst = dst0 + c * SA_STRIDE;
#pragma unroll 6
        for (int jj = q4; jj < SIG_HW + KS - 1; jj += 4) {
            int ix = jj - PADK;
            float v = (vy && ix >= 0 && ix < SIG_HW) ? __ldg(src + ix) : 0.f;
            dst[jj] = __uint_as_float(f2tf(v));
        }
    };

    // weight prefetch: tile q -> 4 float4 regs per thread
    float4 wreg[4];
    auto prefetch_w = [&](int q) {
        const float4* src = (const float4*)(g_w2 + ((size_t)q << 12));
#pragma unroll
        for (int i = 0; i < 4; i++) wreg[i] = __ldg(src + i * 256 + tid);
    };
    auto store_w = [&](int q) {
        float* wb = sW + (q & 1) * SW_TILE_ELEMS;
#pragma unroll
        for (int i = 0; i < 4; i++) {
            const int e  = i * 256 + tid;
            const int o  = e >> 4;
            const int c4 = (e & 15) << 2;
            *(float4*)(wb + o * SW_STRIDE + c4) = wreg[i];
        }
    };

    // prologue: row 0 + weight tile 0
    load_row(0);
    prefetch_w(0);
    __syncthreads();

    const int xb = warp * 32 + g;    // base x (within-frag col offset added later)

    for (int t = 0; t < KS; t++) {
        float* sA0 = sA + (t & 1) * SA_ROW_ELEMS;        // row t   (output y)
        float* sA1 = sA + ((t + 1) & 1) * SA_ROW_ELEMS;  // row t+1 (output y+1)
        for (int kx = 0; kx < KS; kx++) {
            const int q = t * KS + kx;
            if (kx == 0) {
                __syncthreads();          // step t-1 MMAs done -> row ring slot free
                load_row(t + 1);
            }
            store_w(q);
            prefetch_w(q + 1 <= KS * KS - 1 ? q + 1 : q);
            __syncthreads();              // weights(q) + row(t+1) visible; MMA(q-1) done

            const float* wb = sW + (q & 1) * SW_TILE_ELEMS;
            const int colb = xb + kx;
#pragma unroll
            for (int kc = 0; kc < 8; kc++) {
                unsigned a[4][4];
#pragma unroll
                for (int mt = 0; mt < 4; mt++) {
                    const float* p = wb + (mt * 16 + g) * SW_STRIDE + kc * 8 + t4;
                    a[mt][0] = __float_as_uint(p[0]);
                    a[mt][1] = __float_as_uint(p[8 * SW_STRIDE]);
                    a[mt][2] = __float_as_uint(p[4]);
                    a[mt][3] = __float_as_uint(p[8 * SW_STRIDE + 4]);
                }
#pragma unroll
                for (int nt = 0; nt < 4; nt++) {
                    const int off = (kc * 8 + t4) * SA_STRIDE + colb + nt * 8;
                    const unsigned b00 = __float_as_uint(sA0[off]);
                    const unsigned b01 = __float_as_uint(sA0[off + 4 * SA_STRIDE]);
                    const unsigned b10 = __float_as_uint(sA1[off]);
                    const unsigned b11 = __float_as_uint(sA1[off + 4 * SA_STRIDE]);
#pragma unroll
                    for (int mt = 0; mt < 4; mt++) {
                        mma_tf32(&acc[mt][nt][0], a[mt], b00, b01);
                        mma_tf32(&acc[mt][nt][4], a[mt], b10, b11);
                    }
                }
            }
        }
    }

    // epilogue: bias + store out[b][o][y+y01][x]
#pragma unroll
    for (int mt = 0; mt < 4; mt++) {
#pragma unroll
        for (int r = 0; r < 2; r++) {
            const int o = mt * 16 + r * 8 + g;
            const float bv = __ldg(bias + o);
            float* obase = out + (((long)(b * COUT + o)) << 16) + ((long)y << 8)
                         + warp * 32 + t4 * 2;
#pragma unroll
            for (int y01 = 0; y01 < 2; y01++) {
                float* orow = obase + y01 * SIG_HW;
#pragma unroll
                for (int nt = 0; nt < 4; nt++) {
                    float2 v;
                    v.x = acc[mt][nt][y01 * 4 + r * 2 + 0] + bv;
                    v.y = acc[mt][nt][y01 * 4 + r * 2 + 1] + bv;
                    *(float2*)(orow + nt * 8) = v;
                }
            }
        }
    }
}

// ---------------------------------------------------------------------------
extern "C" void kernel_launch(void* const* d_in, const int* in_sizes, int n_in,
                              void* d_out, int out_size) {
    const float* sig  = (const float*)d_in[0];
    const float* w    = (const float*)d_in[1];
    const float* bias = (const float*)d_in[2];
    float* out        = (float*)d_out;

    const int wtot = KS * KS * COUT * CIN;
    prep_weights<<<(wtot + 255) / 256, 256>>>(w);

    const size_t smem_bytes = (size_t)SMEM_FLOATS * sizeof(float);  // 186,368
    cudaFuncSetAttribute(conv_main, cudaFuncAttributeMaxDynamicSharedMemorySize,
                         (int)smem_bytes);
    dim3 grid(SIG_HW / 2, NBATCH);   // 128 y-pairs x 8 batches
    conv_main<<<grid, 256, smem_bytes>>>(sig, bias, out);
}